// round 16
// baseline (speedup 1.0000x reference)
#include <cuda_runtime.h>
#include <math.h>
#include <stdint.h>

#define NQ    20
#define NL    4
#define BATCH 16
#define DIM   (1 << NQ)

__device__ float  g_bufA[BATCH * DIM];   // 64 MB
__device__ float  g_bufB[BATCH * DIM];   // 64 MB
__device__ float2 g_rf[NL * NQ];   // .x = ratio (|r|<=1), .y = form (0 or 1)
__device__ float  g_absC;          // |product of per-gate scales|

// ---------------------------------------------------------------------------
// Fast-Givens precompute.
//   form0 (|c|>=|s|): M = c*[[1,-t],[t,1]], t=s/c
//   form1 (|s|> |c|): M = s*[[u,-1],[1,u]], u=c/s
// ---------------------------------------------------------------------------
__global__ void sincos_kernel(const float* __restrict__ theta) {
    __shared__ float sc[NL * NQ];
    int i = threadIdx.x;
    if (i < NL * NQ) {
        float t = 0.5f * theta[i];
        float c = cosf(t), s = sinf(t);
        bool form = fabsf(s) > fabsf(c);
        g_rf[i] = make_float2(form ? (c / s) : (s / c), form ? 1.0f : 0.0f);
        sc[i] = form ? s : c;
    }
    __syncthreads();
    if (i == 0) {
        float p = 1.0f;
        for (int k = 0; k < NL * NQ; k++) p *= sc[k];
        g_absC = fabsf(p);
    }
}

// ---------------------------------------------------------------------------
// Fast-Givens butterflies. 'a' = role-0 element:
//   form0: a' = a - r*b ; b' = b + r*a
//   form1: a' = r*a - b ; b' = r*b + a
// ---------------------------------------------------------------------------
template <int N>
__device__ __forceinline__ void stage_fg(float* e, int m, float2 rf) {
    float r = rf.x;
    if (rf.y == 0.0f) {
#pragma unroll
        for (int j = 0; j < N; j++)
            if ((j & m) == 0) {
                float a = e[j], b = e[j | m];
                e[j]     = fmaf(-r, b, a);
                e[j | m] = fmaf( r, a, b);
            }
    } else {
#pragma unroll
        for (int j = 0; j < N; j++)
            if ((j & m) == 0) {
                float a = e[j], b = e[j | m];
                e[j]     = fmaf(r, a, -b);
                e[j | m] = fmaf(r, b,  a);
            }
    }
}

__device__ __forceinline__ float xsign(float v, uint32_t sg) {
    return __uint_as_float(__float_as_uint(v) ^ sg);
}

// Conjugated H stage (P^-1 H P): couples u-pairs differing in bits {hb, hb-1};
// role(u) = parity(u >> hb).
template <int HB>
__device__ __forceinline__ void conj_stage(float e[64], float2 rf) {
    const int mask = 3 << (HB - 1);
    float r = rf.x;
    bool f1 = (rf.y != 0.0f);
    if (!f1) {
#pragma unroll
        for (int u = 0; u < 64; u++)
            if ((u & (1 << HB)) == 0) {
                int v = u ^ mask;
                int ra = __popc(u >> HB) & 1;
                int ia = ra ? v : u;
                int ib = ra ? u : v;
                float a = e[ia], b = e[ib];
                e[ia] = fmaf(-r, b, a);
                e[ib] = fmaf( r, a, b);
            }
    } else {
#pragma unroll
        for (int u = 0; u < 64; u++)
            if ((u & (1 << HB)) == 0) {
                int v = u ^ mask;
                int ra = __popc(u >> HB) & 1;
                int ia = ra ? v : u;
                int ib = ra ? u : v;
                float a = e[ia], b = e[ib];
                e[ia] = fmaf(r, a, -b);
                e[ib] = fmaf(r, b,  a);
            }
    }
}

// Conjugated R5(layer1) stage inside hh: couples g bits {14,13} = (reg bit 0,
// lane bit 0). Partner of e[u] is shfl_xor(e[u^1], 1). Role 'a' = parity(u)==0.
__device__ __forceinline__ void conj_r5_stage(float e[64], float2 rf) {
    float r = rf.x;
    bool f1 = (rf.y != 0.0f);
#pragma unroll
    for (int u = 0; u < 64; u += 2) {
        float o0 = __shfl_xor_sync(0xffffffffu, e[u + 1], 1);
        float o1 = __shfl_xor_sync(0xffffffffu, e[u],     1);
        bool aFirst = ((__popc(u) & 1) == 0);
        if (!f1) {
            if (aFirst) {
                e[u]     = fmaf(-r, o0, e[u]);
                e[u + 1] = fmaf( r, o1, e[u + 1]);
            } else {
                e[u]     = fmaf( r, o0, e[u]);
                e[u + 1] = fmaf(-r, o1, e[u + 1]);
            }
        } else {
            if (aFirst) {
                e[u]     = fmaf(r, e[u],     -o0);
                e[u + 1] = fmaf(r, e[u + 1],  o1);
            } else {
                e[u]     = fmaf(r, e[u],      o0);
                e[u + 1] = fmaf(r, e[u + 1], -o1);
            }
        }
    }
}

// gray decode (p such that p ^ (p>>1) = g)
__device__ __host__ __forceinline__ int gdec(int g) {
    int p = g;
    p ^= p >> 1; p ^= p >> 2; p ^= p >> 4; p ^= p >> 8; p ^= p >> 16;
    return p;
}
__device__ __forceinline__ int gd6(int u) {
    int p = u; p ^= p >> 1; p ^= p >> 2; p ^= p >> 4; return p & 63;
}

// ---------------------------------------------------------------------------
// HH kernel: (R5_l1) * H1 * P * (H0 x R5_l0). Orbit = g bits 19:14 in regs;
// pos bit 13 on lane bit 0.  pos = (t0<<13)|(sub<<7)|(w<<4)|t[4:1], grid 1024.
// ---------------------------------------------------------------------------
__global__ void __launch_bounds__(256, 2) hh_kernel(const float* __restrict__ in,
                                                    float* __restrict__ out) {
    cudaGridDependencySynchronize();       // PDL
    const int blk = blockIdx.x;                   // BATCH*64
    const int tid = threadIdx.x;
    const int t0  = tid & 1;
    const int w   = tid >> 5;                     // 0..7
    const int tl  = (tid >> 1) & 15;              // pos bits 3:0
    const int sub = blk & 63;
    const int pos = (t0 << 13) | (sub << 7) | (w << 4) | tl;
    const size_t bbase = (size_t)(blk >> 6) << 20;

    float e[64];
    const float* pin = in + bbase + pos;
#pragma unroll
    for (int u = 0; u < 64; u++) e[u] = pin[u << 14];

    const float2* rf0 = g_rf;           // layer 0
    const float2* rf1 = g_rf + NQ;      // layer 1

    stage_fg<64>(e, 32, rf0[0]);
    stage_fg<64>(e, 16, rf0[1]);
    stage_fg<64>(e,  8, rf0[2]);
    stage_fg<64>(e,  4, rf0[3]);
    stage_fg<64>(e,  2, rf0[4]);
    stage_fg<64>(e,  1, rf0[5]);

    conj_stage<5>(e, rf1[0]);
    conj_stage<4>(e, rf1[1]);
    conj_stage<3>(e, rf1[2]);
    conj_stage<2>(e, rf1[3]);
    conj_stage<1>(e, rf1[4]);
    conj_r5_stage(e, rf1[5]);

    const int A = gdec(pos);
    float* pa = out + bbase + A;
    float* pb = out + bbase + (A ^ 0x3FFF);
#pragma unroll
    for (int u = 0; u < 64; u++) {
        int hi = gd6(u) << 14;
        if (__popc(u) & 1) pb[hi] = e[u];
        else               pa[hi] = e[u];
    }
}

// ---------------------------------------------------------------------------
// PH kernel: (H_l x R5_l) * P over qubits 0..5 (64-element orbit), grid 1024.
// ---------------------------------------------------------------------------
__global__ void __launch_bounds__(256, 2) ph_kernel(const float* __restrict__ in,
                                                    float* __restrict__ out,
                                                    int layer) {
    cudaGridDependencySynchronize();       // PDL
    const int blk = blockIdx.x;                   // BATCH*64
    const int pos = (blk & 63) * 256 + threadIdx.x;   // 14-bit position
    const size_t bbase = (size_t)(blk >> 6) << 20;
    const int G = pos ^ (pos >> 1);

    float e[64];
    const float* pin = in + bbase;
#pragma unroll
    for (int k = 0; k < 64; k++)
        e[k] = pin[((k << 14) ^ (k << 13)) ^ G];

    const float2* rf = g_rf + layer * NQ;
    stage_fg<64>(e, 32, rf[0]);
    stage_fg<64>(e, 16, rf[1]);
    stage_fg<64>(e,  8, rf[2]);
    stage_fg<64>(e,  4, rf[3]);
    stage_fg<64>(e,  2, rf[4]);
    stage_fg<64>(e,  1, rf[5]);

    float* pout = out + bbase + pos;
#pragma unroll
    for (int k = 0; k < 64; k++) pout[k << 14] = e[k];
}

// ---------------------------------------------------------------------------
// LOW14 vectorized zero-shuffle kernel: qubits 6..19 in 16384-float tiles.
// 512 thr x 32 regs, 64 KB smem, 2 CTAs/SM, grid 1024. No warp shuffles.
//  L1: idx = (w@13:10 | t@9:5 | j@4:0)  -> contiguous: 8x LDG.128
//      phase1: q19..15 on j (j bit k <-> qubit 19-k)
//  T1 (vector store, scalar load, XOR-swizzled, conflict-free):
//      store unit  w*256 + t*8 + (jf ^ (t&7))            [STS.128]
//      load  word  4*(w*256 + j'*8 + ((t>>2)^(j'&7))) + (t&3)
//  L2: idx = (w@13:10 | j@9:5 | t@4:0) -> phase2: q14..10 on j
//  T2 (scalar both ways, same swizzle family):
//      store word 4*(w*256 + j*8 + ((t>>2)^(j&7))) + (t&3)
//      load  word 4*(j3l*256 + j3_4*128 + w*8 + ((t>>2)^(w&7))) + (t&3)
//  L3: idx = (j3l@13:10 | j3_4@9 | w@8:5 | t@4:0) -> phase3: q9..6 on j3l
//  Stores lane-contiguous; FINAL folds P + abs*|C| (gdec over disjoint fields).
// ---------------------------------------------------------------------------
template <bool FINAL>
__global__ void __launch_bounds__(512, 2) low14_kernel(const float* in,
                                                       float* out,
                                                       int layer) {
    cudaGridDependencySynchronize();       // PDL
    extern __shared__ float sm[];          // 16384 floats = 64 KB
    float4* sm4 = (float4*)sm;
    const int t = threadIdx.x & 31;
    const int w = threadIdx.x >> 5;        // 0..15
    const int blk = blockIdx.x;            // BATCH*64
    const int tile = blk & 63;
    const size_t bbase = (size_t)(blk >> 6) << 20;
    const size_t tbase = bbase + ((size_t)tile << 14);

    float e[32];
    // L1 load: 8x LDG.128, thread's 32 elements contiguous
    {
        const float4* p4 = (const float4*)(in + tbase + (w << 10) + (t << 5));
#pragma unroll
        for (int jf = 0; jf < 8; jf++) {
            float4 v = p4[jf];
            e[4 * jf + 0] = v.x; e[4 * jf + 1] = v.y;
            e[4 * jf + 2] = v.z; e[4 * jf + 3] = v.w;
        }
    }

    const float2* rf = g_rf + layer * NQ;
    // phase1: q19..15 on j
    stage_fg<32>(e, 1,  rf[19]);
    stage_fg<32>(e, 2,  rf[18]);
    stage_fg<32>(e, 4,  rf[17]);
    stage_fg<32>(e, 8,  rf[16]);
    stage_fg<32>(e, 16, rf[15]);

    // T1: vector store, scalar transposed load
#pragma unroll
    for (int jf = 0; jf < 8; jf++) {
        sm4[(w << 8) | (t << 3) | (jf ^ (t & 7))] =
            make_float4(e[4 * jf], e[4 * jf + 1], e[4 * jf + 2], e[4 * jf + 3]);
    }
    __syncthreads();
#pragma unroll
    for (int j = 0; j < 32; j++)
        e[j] = sm[(((w << 8) | (j << 3) | ((t >> 2) ^ (j & 7))) << 2) | (t & 3)];

    // phase2: q14..10 on j
    stage_fg<32>(e, 1,  rf[14]);
    stage_fg<32>(e, 2,  rf[13]);
    stage_fg<32>(e, 4,  rf[12]);
    stage_fg<32>(e, 8,  rf[11]);
    stage_fg<32>(e, 16, rf[10]);

    // T2: scalar both ways
    __syncthreads();                       // all T1 loads done before overwrite
#pragma unroll
    for (int j = 0; j < 32; j++)
        sm[(((w << 8) | (j << 3) | ((t >> 2) ^ (j & 7))) << 2) | (t & 3)] = e[j];
    __syncthreads();
#pragma unroll
    for (int j3 = 0; j3 < 32; j3++) {
        int j3l = j3 & 15, j34 = j3 >> 4;
        e[j3] = sm[(((j3l << 8) | (j34 << 7) | (w << 3) | ((t >> 2) ^ (w & 7))) << 2) | (t & 3)];
    }

    // phase3: q9..6 on j3l (j3 bit4 = q10, done in phase2 -> inert)
    stage_fg<32>(e, 1, rf[9]);
    stage_fg<32>(e, 2, rf[8]);
    stage_fg<32>(e, 4, rf[7]);
    stage_fg<32>(e, 8, rf[6]);

    if (FINAL) {
        const int   pbase = gdec((tile << 14) | (w << 5) | t);
        const float absC  = g_absC;
#pragma unroll
        for (int j3 = 0; j3 < 32; j3++) {
            int j3l = j3 & 15, j34 = j3 >> 4;
            int cj = gdec((j3l << 10) | (j34 << 9));   // const per j3
            out[bbase + (pbase ^ cj)] = fabsf(e[j3]) * absC;
        }
    } else {
        float* q = out + tbase;
#pragma unroll
        for (int j3 = 0; j3 < 32; j3++) {
            int j3l = j3 & 15, j34 = j3 >> 4;
            q[(j3l << 10) | (j34 << 9) | (w << 5) | t] = e[j3];
        }
    }
}

// ---------------------------------------------------------------------------
// Host: de-chunked 7-pass pipeline, grid 1024 (multi-wave), PDL boundaries.
// ---------------------------------------------------------------------------
static cudaLaunchAttribute g_pdl_attr[1];

static inline cudaLaunchConfig_t mkcfg(unsigned grid, unsigned block, size_t smem) {
    cudaLaunchConfig_t c{};
    c.gridDim  = dim3(grid, 1, 1);
    c.blockDim = dim3(block, 1, 1);
    c.dynamicSmemBytes = smem;
    c.stream = 0;
    g_pdl_attr[0].id = cudaLaunchAttributeProgrammaticStreamSerialization;
    g_pdl_attr[0].val.programmaticStreamSerializationAllowed = 1;
    c.attrs = g_pdl_attr;
    c.numAttrs = 1;
    return c;
}

extern "C" void kernel_launch(void* const* d_in, const int* in_sizes, int n_in,
                              void* d_out, int out_size) {
    const float* x     = (const float*)d_in[0];
    const float* theta = (const float*)d_in[1];
    float*       out   = (float*)d_out;

    float *bA = nullptr, *bB = nullptr;
    cudaGetSymbolAddress((void**)&bA, g_bufA);
    cudaGetSymbolAddress((void**)&bB, g_bufB);

    const int SM14 = 16384 * sizeof(float);
    cudaFuncSetAttribute(low14_kernel<false>, cudaFuncAttributeMaxDynamicSharedMemorySize, SM14);
    cudaFuncSetAttribute(low14_kernel<true>,  cudaFuncAttributeMaxDynamicSharedMemorySize, SM14);

    sincos_kernel<<<1, 128>>>(theta);

    const int G = BATCH * 64;   // 1024 blocks for every pass

    cudaLaunchConfig_t cL = mkcfg(G, 512, SM14);  // low14
    cudaLaunchConfig_t cH = mkcfg(G, 256, 0);     // hh / ph

    cudaLaunchKernelEx(&cL, low14_kernel<false>, x, bA, 0);                // L0
    cudaLaunchKernelEx(&cH, hh_kernel, (const float*)bA, bB);              // H1*P*H0'
    cudaLaunchKernelEx(&cL, low14_kernel<false>, (const float*)bB, bB, 1); // L1 (in-place)
    cudaLaunchKernelEx(&cH, ph_kernel, (const float*)bB, bA, 2);           // (H2,R5l2)*P
    cudaLaunchKernelEx(&cL, low14_kernel<false>, (const float*)bA, bA, 2); // L2 (in-place)
    cudaLaunchKernelEx(&cH, ph_kernel, (const float*)bA, bB, 3);           // (H3,R5l3)*P
    cudaLaunchKernelEx(&cL, low14_kernel<true>,  (const float*)bB, out, 3); // P*L3
}

// round 17
// speedup vs baseline: 1.3340x; 1.3340x over previous
#include <cuda_runtime.h>
#include <math.h>
#include <stdint.h>

#define NQ    20
#define NL    4
#define BATCH 16
#define DIM   (1 << NQ)
#define HALF  8                     // batches per stream-half

__device__ float  g_bufA[BATCH * DIM];   // 64 MB (halves split between streams)
__device__ float  g_bufB[BATCH * DIM];   // 64 MB
__device__ float2 g_rf[NL * NQ];   // .x = ratio (|r|<=1), .y = form (0 or 1)
__device__ float  g_absC;          // |product of per-gate scales|

// ---------------------------------------------------------------------------
// Fast-Givens precompute.
// ---------------------------------------------------------------------------
__global__ void sincos_kernel(const float* __restrict__ theta) {
    __shared__ float sc[NL * NQ];
    int i = threadIdx.x;
    if (i < NL * NQ) {
        float t = 0.5f * theta[i];
        float c = cosf(t), s = sinf(t);
        bool form = fabsf(s) > fabsf(c);
        g_rf[i] = make_float2(form ? (c / s) : (s / c), form ? 1.0f : 0.0f);
        sc[i] = form ? s : c;
    }
    __syncthreads();
    if (i == 0) {
        float p = 1.0f;
        for (int k = 0; k < NL * NQ; k++) p *= sc[k];
        g_absC = fabsf(p);
    }
}

// ---------------------------------------------------------------------------
// Fast-Givens butterflies. 'a' = role-0 element:
//   form0: a' = a - r*b ; b' = b + r*a
//   form1: a' = r*a - b ; b' = r*b + a
// ---------------------------------------------------------------------------
template <int N>
__device__ __forceinline__ void stage_fg(float* e, int m, float2 rf) {
    float r = rf.x;
    if (rf.y == 0.0f) {
#pragma unroll
        for (int j = 0; j < N; j++)
            if ((j & m) == 0) {
                float a = e[j], b = e[j | m];
                e[j]     = fmaf(-r, b, a);
                e[j | m] = fmaf( r, a, b);
            }
    } else {
#pragma unroll
        for (int j = 0; j < N; j++)
            if ((j & m) == 0) {
                float a = e[j], b = e[j | m];
                e[j]     = fmaf(r, a, -b);
                e[j | m] = fmaf(r, b,  a);
            }
    }
}

__device__ __forceinline__ float xsign(float v, uint32_t sg) {
    return __uint_as_float(__float_as_uint(v) ^ sg);
}

// Conjugated H stage (P^-1 H P): couples u-pairs differing in bits {hb, hb-1};
// role(u) = parity(u >> hb).
template <int HB>
__device__ __forceinline__ void conj_stage(float e[64], float2 rf) {
    const int mask = 3 << (HB - 1);
    float r = rf.x;
    bool f1 = (rf.y != 0.0f);
    if (!f1) {
#pragma unroll
        for (int u = 0; u < 64; u++)
            if ((u & (1 << HB)) == 0) {
                int v = u ^ mask;
                int ra = __popc(u >> HB) & 1;
                int ia = ra ? v : u;
                int ib = ra ? u : v;
                float a = e[ia], b = e[ib];
                e[ia] = fmaf(-r, b, a);
                e[ib] = fmaf( r, a, b);
            }
    } else {
#pragma unroll
        for (int u = 0; u < 64; u++)
            if ((u & (1 << HB)) == 0) {
                int v = u ^ mask;
                int ra = __popc(u >> HB) & 1;
                int ia = ra ? v : u;
                int ib = ra ? u : v;
                float a = e[ia], b = e[ib];
                e[ia] = fmaf(r, a, -b);
                e[ib] = fmaf(r, b,  a);
            }
    }
}

// Conjugated R5(layer1) stage inside hh: couples g bits {14,13} = (reg bit 0,
// lane bit 0). Partner of e[u] is shfl_xor(e[u^1], 1). Role 'a' = parity(u)==0.
__device__ __forceinline__ void conj_r5_stage(float e[64], float2 rf) {
    float r = rf.x;
    bool f1 = (rf.y != 0.0f);
#pragma unroll
    for (int u = 0; u < 64; u += 2) {
        float o0 = __shfl_xor_sync(0xffffffffu, e[u + 1], 1);
        float o1 = __shfl_xor_sync(0xffffffffu, e[u],     1);
        bool aFirst = ((__popc(u) & 1) == 0);
        if (!f1) {
            if (aFirst) {
                e[u]     = fmaf(-r, o0, e[u]);
                e[u + 1] = fmaf( r, o1, e[u + 1]);
            } else {
                e[u]     = fmaf( r, o0, e[u]);
                e[u + 1] = fmaf(-r, o1, e[u + 1]);
            }
        } else {
            if (aFirst) {
                e[u]     = fmaf(r, e[u],     -o0);
                e[u + 1] = fmaf(r, e[u + 1],  o1);
            } else {
                e[u]     = fmaf(r, e[u],      o0);
                e[u + 1] = fmaf(r, e[u + 1], -o1);
            }
        }
    }
}

// gray decode (p such that p ^ (p>>1) = g)
__device__ __host__ __forceinline__ int gdec(int g) {
    int p = g;
    p ^= p >> 1; p ^= p >> 2; p ^= p >> 4; p ^= p >> 8; p ^= p >> 16;
    return p;
}
__device__ __forceinline__ int gd6(int u) {
    int p = u; p ^= p >> 1; p ^= p >> 2; p ^= p >> 4; return p & 63;
}

// ---------------------------------------------------------------------------
// HH kernel: (R5_l1) * H1 * P * (H0 x R5_l0). Orbit = g bits 19:14 in regs;
// pos bit 13 on lane bit 0.  pos = (t0<<13)|(sub<<7)|(w<<4)|t[4:1].
// grid = HALF*64 per stream-half.
// ---------------------------------------------------------------------------
__global__ void __launch_bounds__(256, 2) hh_kernel(const float* __restrict__ in,
                                                    float* __restrict__ out) {
    cudaGridDependencySynchronize();       // PDL
    const int blk = blockIdx.x;
    const int tid = threadIdx.x;
    const int t0  = tid & 1;
    const int w   = tid >> 5;                     // 0..7
    const int tl  = (tid >> 1) & 15;              // pos bits 3:0
    const int sub = blk & 63;
    const int pos = (t0 << 13) | (sub << 7) | (w << 4) | tl;
    const size_t bbase = (size_t)(blk >> 6) << 20;

    float e[64];
    const float* pin = in + bbase + pos;
#pragma unroll
    for (int u = 0; u < 64; u++) e[u] = pin[u << 14];

    const float2* rf0 = g_rf;           // layer 0
    const float2* rf1 = g_rf + NQ;      // layer 1

    stage_fg<64>(e, 32, rf0[0]);
    stage_fg<64>(e, 16, rf0[1]);
    stage_fg<64>(e,  8, rf0[2]);
    stage_fg<64>(e,  4, rf0[3]);
    stage_fg<64>(e,  2, rf0[4]);
    stage_fg<64>(e,  1, rf0[5]);

    conj_stage<5>(e, rf1[0]);
    conj_stage<4>(e, rf1[1]);
    conj_stage<3>(e, rf1[2]);
    conj_stage<2>(e, rf1[3]);
    conj_stage<1>(e, rf1[4]);
    conj_r5_stage(e, rf1[5]);

    const int A = gdec(pos);
    float* pa = out + bbase + A;
    float* pb = out + bbase + (A ^ 0x3FFF);
#pragma unroll
    for (int u = 0; u < 64; u++) {
        int hi = gd6(u) << 14;
        if (__popc(u) & 1) pb[hi] = e[u];
        else               pa[hi] = e[u];
    }
}

// ---------------------------------------------------------------------------
// PH kernel: (H_l x R5_l) * P over qubits 0..5 (64-element orbit).
// ---------------------------------------------------------------------------
__global__ void __launch_bounds__(256, 2) ph_kernel(const float* __restrict__ in,
                                                    float* __restrict__ out,
                                                    int layer) {
    cudaGridDependencySynchronize();       // PDL
    const int blk = blockIdx.x;
    const int pos = (blk & 63) * 256 + threadIdx.x;   // 14-bit position
    const size_t bbase = (size_t)(blk >> 6) << 20;
    const int G = pos ^ (pos >> 1);

    float e[64];
    const float* pin = in + bbase;
#pragma unroll
    for (int k = 0; k < 64; k++)
        e[k] = pin[((k << 14) ^ (k << 13)) ^ G];

    const float2* rf = g_rf + layer * NQ;
    stage_fg<64>(e, 32, rf[0]);
    stage_fg<64>(e, 16, rf[1]);
    stage_fg<64>(e,  8, rf[2]);
    stage_fg<64>(e,  4, rf[3]);
    stage_fg<64>(e,  2, rf[4]);
    stage_fg<64>(e,  1, rf[5]);

    float* pout = out + bbase + pos;
#pragma unroll
    for (int k = 0; k < 64; k++) pout[k << 14] = e[k];
}

// ---------------------------------------------------------------------------
// LOW14 zero-shuffle kernel (R15-proven form): qubits 6..19 in 16384-float
// tiles. 512 thr x 32 regs, 64 KB smem, 2 CTAs/SM. No warp shuffles.
//  L1: idx = (j@13:9, w@8:5, t@4:0)  -> phase1: q6..10 on j
//  T1 (j<->t): store phys (j<<9)|(w<<5)|(t^j); load (t<<9)|(w<<5)|(j^t)
//  L2: idx = (t@13:9, w@8:5, j@4:0)  -> phase2: q19..15 on j
//  T2: store back same phys; load (key<<9)|(jl<<5)|(t^key), key=(w<<1)|(j>>4)
//  L3: idx = (w@13:10, j4@9, j[3:0]@8:5, t@4:0) -> phase3: q14..11 on j[3:0]
// ---------------------------------------------------------------------------
template <bool FINAL>
__global__ void __launch_bounds__(512, 2) low14_kernel(const float* in,
                                                       float* out,
                                                       int layer) {
    cudaGridDependencySynchronize();       // PDL
    extern __shared__ float sm[];          // 16384 floats = 64 KB
    const int t = threadIdx.x & 31;
    const int w = threadIdx.x >> 5;        // 0..15
    const int blk = blockIdx.x;
    const int tile = blk & 63;
    const size_t bbase = (size_t)(blk >> 6) << 20;
    const size_t tbase = bbase + ((size_t)tile << 14);

    float e[32];
    const float* p = in + tbase;
#pragma unroll
    for (int j = 0; j < 32; j++) e[j] = p[(j << 9) | (w << 5) | t];

    const float2* rf = g_rf + layer * NQ;
    // phase1: q6..10 on j (L1)
    stage_fg<32>(e, 16, rf[6]);
    stage_fg<32>(e,  8, rf[7]);
    stage_fg<32>(e,  4, rf[8]);
    stage_fg<32>(e,  2, rf[9]);
    stage_fg<32>(e,  1, rf[10]);

    // T1: j <-> t
#pragma unroll
    for (int j = 0; j < 32; j++) sm[(j << 9) | (w << 5) | (t ^ j)] = e[j];
    __syncthreads();
#pragma unroll
    for (int j = 0; j < 32; j++) e[j] = sm[(t << 9) | (w << 5) | (j ^ t)];

    // phase2: q19..15 on j (L2)
    stage_fg<32>(e, 1,  rf[19]);
    stage_fg<32>(e, 2,  rf[18]);
    stage_fg<32>(e, 4,  rf[17]);
    stage_fg<32>(e, 8,  rf[16]);
    stage_fg<32>(e, 16, rf[15]);

    // T2: bring w-field into j[3:0]
    __syncthreads();                       // all T1 loads done before overwrite
#pragma unroll
    for (int j = 0; j < 32; j++) sm[(t << 9) | (w << 5) | (j ^ t)] = e[j];
    __syncthreads();
#pragma unroll
    for (int j = 0; j < 32; j++) {
        int key = ((w << 1) | (j >> 4)) & 31;
        e[j] = sm[(key << 9) | ((j & 15) << 5) | (t ^ key)];
    }

    // phase3: q14..11 on j[3:0] (L3); j[4] inert (q10 done in phase1)
    stage_fg<32>(e, 1, rf[14]);
    stage_fg<32>(e, 2, rf[13]);
    stage_fg<32>(e, 4, rf[12]);
    stage_fg<32>(e, 8, rf[11]);

    if (FINAL) {
        const int   pbase = gdec((tile << 14) | (w << 10) | t);
        const float absC  = g_absC;
#pragma unroll
        for (int j = 0; j < 32; j++) {
            int cj = gdec(((j >> 4) << 9) | ((j & 15) << 5));  // const per j
            out[bbase + (pbase ^ cj)] = fabsf(e[j]) * absC;
        }
    } else {
        float* q = out + tbase;
#pragma unroll
        for (int j = 0; j < 32; j++)
            q[(w << 10) | ((j >> 4) << 9) | ((j & 15) << 5) | t] = e[j];
    }
}

// ---------------------------------------------------------------------------
// Host: two independent 8-batch halves on two streams (fork/join via events,
// graph-capturable). Each half = the proven 7-pass PDL chain, grid 512.
// Streams/events are created at static-init time (before any mem checkpoint);
// no device memory is allocated here.
// ---------------------------------------------------------------------------
struct PipeRes {
    cudaStream_t s1;
    cudaEvent_t  evFork, evJoin;
    PipeRes() {
        cudaStreamCreateWithFlags(&s1, cudaStreamNonBlocking);
        cudaEventCreateWithFlags(&evFork, cudaEventDisableTiming);
        cudaEventCreateWithFlags(&evJoin, cudaEventDisableTiming);
    }
};
static PipeRes g_res;

static cudaLaunchAttribute g_pdl_attr[1];

static inline cudaLaunchConfig_t mkcfg(unsigned grid, unsigned block,
                                       size_t smem, cudaStream_t st) {
    cudaLaunchConfig_t c{};
    c.gridDim  = dim3(grid, 1, 1);
    c.blockDim = dim3(block, 1, 1);
    c.dynamicSmemBytes = smem;
    c.stream = st;
    g_pdl_attr[0].id = cudaLaunchAttributeProgrammaticStreamSerialization;
    g_pdl_attr[0].val.programmaticStreamSerializationAllowed = 1;
    c.attrs = g_pdl_attr;
    c.numAttrs = 1;
    return c;
}

// Launch the full 7-pass chain for one half on one stream.
static void run_half(cudaStream_t st, const float* xh, float* oh,
                     float* bAh, float* bBh, int SM14) {
    const int G = HALF * 64;   // 512 blocks
    cudaLaunchConfig_t cL = mkcfg(G, 512, SM14, st);
    cudaLaunchConfig_t cH = mkcfg(G, 256, 0,    st);

    cudaLaunchKernelEx(&cL, low14_kernel<false>, xh, bAh, 0);                 // L0
    cudaLaunchKernelEx(&cH, hh_kernel, (const float*)bAh, bBh);               // H1*P*H0'
    cudaLaunchKernelEx(&cL, low14_kernel<false>, (const float*)bBh, bBh, 1);  // L1
    cudaLaunchKernelEx(&cH, ph_kernel, (const float*)bBh, bAh, 2);            // (H2,R5)*P
    cudaLaunchKernelEx(&cL, low14_kernel<false>, (const float*)bAh, bAh, 2);  // L2
    cudaLaunchKernelEx(&cH, ph_kernel, (const float*)bAh, bBh, 3);            // (H3,R5)*P
    cudaLaunchKernelEx(&cL, low14_kernel<true>,  (const float*)bBh, oh, 3);   // P*L3
}

extern "C" void kernel_launch(void* const* d_in, const int* in_sizes, int n_in,
                              void* d_out, int out_size) {
    const float* x     = (const float*)d_in[0];
    const float* theta = (const float*)d_in[1];
    float*       out   = (float*)d_out;

    float *bA = nullptr, *bB = nullptr;
    cudaGetSymbolAddress((void**)&bA, g_bufA);
    cudaGetSymbolAddress((void**)&bB, g_bufB);

    const int SM14 = 16384 * sizeof(float);
    cudaFuncSetAttribute(low14_kernel<false>, cudaFuncAttributeMaxDynamicSharedMemorySize, SM14);
    cudaFuncSetAttribute(low14_kernel<true>,  cudaFuncAttributeMaxDynamicSharedMemorySize, SM14);

    const size_t HOFF = (size_t)HALF << 20;   // 8 batches of floats

    // Coefficients on the main (captured) stream, then fork.
    sincos_kernel<<<1, 128>>>(theta);
    cudaEventRecord(g_res.evFork, 0);
    cudaStreamWaitEvent(g_res.s1, g_res.evFork, 0);

    // Half A (batches 0..7) on the main stream; half B (8..15) on s1.
    run_half(0,        x,        out,        bA,        bB,        SM14);
    run_half(g_res.s1, x + HOFF, out + HOFF, bA + HOFF, bB + HOFF, SM14);

    // Join s1 back into the captured stream.
    cudaEventRecord(g_res.evJoin, g_res.s1);
    cudaStreamWaitEvent(0, g_res.evJoin, 0);
}